// round 10
// baseline (speedup 1.0000x reference)
#include <cuda_runtime.h>
#include <cstdint>

#define DI __device__ __forceinline__

constexpr int D = 128, G = 8, F = 80, A = 18;
constexpr int BM = 128, THREADS = 256;

constexpr int HS  = 84;   // H stride: 84 % 8 == 4 -> conflict-free 32-bit frags
constexpr int WP  = 40;   // pair-permuted weight stride: 40 % 32 == 8 -> conflict-free LDS.64
constexpr int SS  = 36;   // state-quarter stride: 36 % 8 == 4 -> conflict-free LDS.32

constexpr int W_FL   = F * WP;        // 3200 floats (weight region of a slot)
constexpr int S_FL   = BM * SS;       // 4608 floats (state region of a slot)
constexpr int SLOT   = W_FL + S_FL;   // 7808 floats per slot
constexpr int OFF_H  = 0;                     // 128*84 = 10752
constexpr int OFF_SL = BM * HS;               // 2 slots
constexpr int OFF_SB = OFF_SL + 2 * SLOT;     // b2(80)+b3(80)
constexpr int SMEM_FLOATS = OFF_SB + 2 * F;
constexpr int SMEM_BYTES  = SMEM_FLOATS * 4;  // 106112 B -> 2 CTAs/SM

// pair-permuted, tf32-rounded weight images (layout == staged layout)
__device__ __align__(16) float g_W1p[G * 4 * F * WP];   // [g][q][n][40]
__device__ __align__(16) float g_W23p[2 * 2 * F * WP];  // [l][h][n][40]
__device__ __align__(16) float g_W4p[G * 2 * A * WP];   // [g][h][n][40]

DI uint32_t tf32b(float x) {
    uint32_t r; asm("cvt.rna.tf32.f32 %0, %1;" : "=r"(r) : "f"(x));
    return r;
}
DI float tf32f(float x) { return __uint_as_float(tf32b(x)); }

DI void mma8(float* c, uint32_t a0, uint32_t a1, uint32_t a2, uint32_t a3,
             uint32_t b0, uint32_t b1) {
    asm("mma.sync.aligned.m16n8k8.row.col.f32.tf32.tf32.f32 "
        "{%0,%1,%2,%3}, {%4,%5,%6,%7}, {%8,%9}, {%0,%1,%2,%3};"
        : "+f"(c[0]), "+f"(c[1]), "+f"(c[2]), "+f"(c[3])
        : "r"(a0), "r"(a1), "r"(a2), "r"(a3), "r"(b0), "r"(b1));
}

DI void cpa16(uint32_t dst, const float* src) {
    asm volatile("cp.async.cg.shared.global [%0], [%1], 16;" :: "r"(dst), "l"(src));
}
#define CPA_COMMIT() asm volatile("cp.async.commit_group;" ::: "memory")
#define CPA_WAIT1()  asm volatile("cp.async.wait_group 1;" ::: "memory")

// data k-index j -> pair-permuted position within its 8-block:
// pos = (j & ~7) + 2*(j&3) + ((j>>2)&1)   (pairs (k, k+4) adjacent)
__global__ void prep_kernel(const float* __restrict__ W1, const float* __restrict__ W2,
                            const float* __restrict__ W3, const float* __restrict__ W4) {
    int i = blockIdx.x * blockDim.x + threadIdx.x;
    if (i < G * 4 * F * 32) {  // i = ((g*4+q)*F + n)*32 + j
        int j = i & 31; int q2 = i >> 5;
        int n = q2 % F; q2 /= F;
        int q = q2 & 3; int g = q2 >> 2;
        int pos = (j & ~7) + 2 * (j & 3) + ((j >> 2) & 1);
        g_W1p[((g * 4 + q) * F + n) * WP + pos] =
            tf32f(W1[(size_t)(g * F + n) * D + q * 32 + j]);
    }
    if (i < 2 * 2 * F * 40) {  // i = ((l*2+h)*F + n)*40 + j
        int j = i % 40; int q2 = i / 40;
        int n = q2 % F; q2 /= F;
        int h = q2 & 1; int l = q2 >> 1;
        int pos = (j & ~7) + 2 * (j & 3) + ((j >> 2) & 1);
        const float* W = l ? W3 : W2;
        g_W23p[((l * 2 + h) * F + n) * WP + pos] = tf32f(W[n * F + h * 40 + j]);
    }
    if (i < G * 2 * A * 40) {  // i = ((g*2+h)*A + n)*40 + j
        int j = i % 40; int q2 = i / 40;
        int n = q2 % A; q2 /= A;
        int h = q2 & 1; int g = q2 >> 1;
        int pos = (j & ~7) + 2 * (j & 3) + ((j >> 2) & 1);
        g_W4p[((g * 2 + h) * A + n) * WP + pos] =
            tf32f(W4[(size_t)(g * A + n) * F + h * 40 + j]);
    }
}

// prefetch stage s into slot s&1
DI void issue_stage(int s, int gLo, int nG, uint32_t slbase, int tid,
                    const float* state, int mBase, int nTotal) {
    uint32_t dst = slbase + (uint32_t)(s & 1) * (SLOT * 4);
    if (s < 4 * nG) {
        int g = gLo + (s >> 2), q = s & 3;
        // W1 quarter: linear copy, 800 float4
        const float* src = g_W1p + (size_t)(g * 4 + q) * F * WP;
        #pragma unroll
        for (int c = tid; c < 800; c += THREADS)
            cpa16(dst + c * 16, src + c * 4);
        // state quarter: 128 rows x 32 floats -> stride SS
        uint32_t sdst = dst + W_FL * 4;
        #pragma unroll
        for (int c = tid; c < 1024; c += THREADS) {
            int m = c >> 3, cc = c & 7;
            int row = min(mBase + m, nTotal - 1);
            cpa16(sdst + (m * SS + cc * 4) * 4, state + (size_t)row * D + q * 32 + cc * 4);
        }
    } else {
        int t = s - 4 * nG;
        const float* src; int nch;
        if (t < 4) { src = g_W23p + (size_t)t * F * WP; nch = 800; }
        else {
            int u = t - 4; int g = gLo + (u >> 1), h = u & 1;
            src = g_W4p + (size_t)(g * 2 + h) * A * WP; nch = A * 10;
        }
        for (int c = tid; c < nch; c += THREADS)
            cpa16(dst + c * 16, src + c * 4);
    }
}

__global__ __launch_bounds__(THREADS, 2)
void fused_kernel(const float* __restrict__ state, const int* __restrict__ idx,
                  const float* __restrict__ b1, const float* __restrict__ b2,
                  const float* __restrict__ b3, const float* __restrict__ b4,
                  float* __restrict__ out, int nTotal)
{
    extern __shared__ float sm[];
    float* H  = sm + OFF_H;
    float* sb = sm + OFF_SB;  // [0..79]=b2, [80..159]=b3

    uint32_t su;
    asm("{ .reg .u64 t; cvta.to.shared.u64 t, %1; cvt.u32.u64 %0, t; }"
        : "=r"(su) : "l"(sm));
    const uint32_t slbase = su + OFF_SL * 4;

    const int tid  = threadIdx.x;
    const int lane = tid & 31;
    const int wid  = tid >> 5;
    const int gid  = lane >> 2;
    const int tig  = lane & 3;

    // 4 m-warps x 2 n-warps; warp: 2 m16 tiles x 5 n-tiles (40 cols)
    const int mw = wid & 3;
    const int nw = wid >> 2;
    const int nbase = nw * 40;
    const int rA0 = mw * 32 + gid;
    const int rA1 = mw * 32 + 16 + gid;

    const int mBase  = blockIdx.x * BM;
    const int nValid = min(BM, nTotal - mBase);

    const int gLo = __ldg(&idx[mBase]);
    const int gHi = __ldg(&idx[mBase + nValid - 1]);
    const int nG = gHi - gLo + 1;
    const int nStages = 6 * nG + 4;

    int mg[2][2];
    mg[0][0] = (rA0     < nValid) ? __ldg(&idx[mBase + rA0])     : -1;
    mg[0][1] = (rA0 + 8 < nValid) ? __ldg(&idx[mBase + rA0 + 8]) : -1;
    mg[1][0] = (rA1     < nValid) ? __ldg(&idx[mBase + rA1])     : -1;
    mg[1][1] = (rA1 + 8 < nValid) ? __ldg(&idx[mBase + rA1 + 8]) : -1;

    if (tid < 2 * F) sb[tid] = (tid < F) ? b2[tid] : b3[tid - F];

    issue_stage(0, gLo, nG, slbase, tid, state, mBase, nTotal);
    CPA_COMMIT();

    float acc[2][5][4];

    for (int s = 0; s < nStages; ++s) {
        if (s + 1 < nStages)
            issue_stage(s + 1, gLo, nG, slbase, tid, state, mBase, nTotal);
        CPA_COMMIT();  // ALWAYS commit (empty groups at tail keep wait_group counts aligned)
        CPA_WAIT1();
        __syncthreads();  // stage s data visible to all
        const float* SWp = sm + OFF_SL + (s & 1) * SLOT;   // weight region
        const float* SP  = SWp + W_FL;                      // state region

        if (s < 4 * nG) {
            // ---------- Layer 1, quarter q of game g ----------
            int g = gLo + (s >> 2), q = s & 3;
            if (q == 0) {
                #pragma unroll
                for (int t = 0; t < 2; ++t)
                    #pragma unroll
                    for (int nt = 0; nt < 5; ++nt)
                        #pragma unroll
                        for (int i = 0; i < 4; ++i) acc[t][nt][i] = 0.f;
            }
            #pragma unroll
            for (int kl = 0; kl < 4; ++kl) {
                uint32_t af[2][4];
                af[0][0] = tf32b(SP[rA0 * SS + kl * 8 + tig]);
                af[0][1] = tf32b(SP[(rA0 + 8) * SS + kl * 8 + tig]);
                af[0][2] = tf32b(SP[rA0 * SS + kl * 8 + tig + 4]);
                af[0][3] = tf32b(SP[(rA0 + 8) * SS + kl * 8 + tig + 4]);
                af[1][0] = tf32b(SP[rA1 * SS + kl * 8 + tig]);
                af[1][1] = tf32b(SP[(rA1 + 8) * SS + kl * 8 + tig]);
                af[1][2] = tf32b(SP[rA1 * SS + kl * 8 + tig + 4]);
                af[1][3] = tf32b(SP[(rA1 + 8) * SS + kl * 8 + tig + 4]);
                #pragma unroll
                for (int nt = 0; nt < 5; ++nt) {
                    float2 bp = *(const float2*)(SWp + (nbase + nt * 8 + gid) * WP + kl * 8 + 2 * tig);
                    uint32_t b0 = __float_as_uint(bp.x);
                    uint32_t bv = __float_as_uint(bp.y);
                    mma8(acc[0][nt], af[0][0], af[0][1], af[0][2], af[0][3], b0, bv);
                    mma8(acc[1][nt], af[1][0], af[1][1], af[1][2], af[1][3], b0, bv);
                }
            }
            if (q == 3) {  // masked epilogue -> H (tf32-rounded); no concurrent H readers
                #pragma unroll
                for (int t = 0; t < 2; ++t) {
                    int rr = (t == 0) ? rA0 : rA1;
                    #pragma unroll
                    for (int hf = 0; hf < 2; ++hf) {
                        if (mg[t][hf] == g) {
                            int row = rr + hf * 8;
                            #pragma unroll
                            for (int nt = 0; nt < 5; ++nt) {
                                int c = nbase + nt * 8 + 2 * tig;
                                float2 w = make_float2(
                                    tf32f(fmaxf(acc[t][nt][2 * hf]     + __ldg(&b1[g * F + c]),     0.f)),
                                    tf32f(fmaxf(acc[t][nt][2 * hf + 1] + __ldg(&b1[g * F + c + 1]), 0.f)));
                                *(float2*)(H + row * HS + c) = w;
                            }
                        }
                    }
                }
            }
        } else if (s - 4 * nG < 4) {
            // ---------- Layers 2 & 3, half h ----------
            int t4 = s - 4 * nG;
            int l = t4 >> 1, h = t4 & 1;
            if (h == 0) {
                #pragma unroll
                for (int t = 0; t < 2; ++t)
                    #pragma unroll
                    for (int nt = 0; nt < 5; ++nt)
                        #pragma unroll
                        for (int i = 0; i < 4; ++i) acc[t][nt][i] = 0.f;
            }
            #pragma unroll
            for (int kl = 0; kl < 5; ++kl) {
                int kb = h * 40 + kl * 8;
                uint32_t af[2][4];
                af[0][0] = __float_as_uint(H[rA0 * HS + kb + tig]);
                af[0][1] = __float_as_uint(H[(rA0 + 8) * HS + kb + tig]);
                af[0][2] = __float_as_uint(H[rA0 * HS + kb + tig + 4]);
                af[0][3] = __float_as_uint(H[(rA0 + 8) * HS + kb + tig + 4]);
                af[1][0] = __float_as_uint(H[rA1 * HS + kb + tig]);
                af[1][1] = __float_as_uint(H[(rA1 + 8) * HS + kb + tig]);
                af[1][2] = __float_as_uint(H[rA1 * HS + kb + tig + 4]);
                af[1][3] = __float_as_uint(H[(rA1 + 8) * HS + kb + tig + 4]);
                #pragma unroll
                for (int nt = 0; nt < 5; ++nt) {
                    float2 bp = *(const float2*)(SWp + (nbase + nt * 8 + gid) * WP + kl * 8 + 2 * tig);
                    uint32_t b0 = __float_as_uint(bp.x);
                    uint32_t bv = __float_as_uint(bp.y);
                    mma8(acc[0][nt], af[0][0], af[0][1], af[0][2], af[0][3], b0, bv);
                    mma8(acc[1][nt], af[1][0], af[1][1], af[1][2], af[1][3], b0, bv);
                }
            }
            if (h == 1) {
                // In-place update of H: warps sharing the same rows (nw=0/1) must ALL
                // finish reading the old values before anyone overwrites them.
                __syncthreads();
                #pragma unroll
                for (int t = 0; t < 2; ++t) {
                    int rr = (t == 0) ? rA0 : rA1;
                    #pragma unroll
                    for (int nt = 0; nt < 5; ++nt) {
                        int c = nbase + nt * 8 + 2 * tig;
                        float2 w0 = make_float2(
                            tf32f(fmaxf(acc[t][nt][0] + sb[l * F + c], 0.f)),
                            tf32f(fmaxf(acc[t][nt][1] + sb[l * F + c + 1], 0.f)));
                        float2 w1 = make_float2(
                            tf32f(fmaxf(acc[t][nt][2] + sb[l * F + c], 0.f)),
                            tf32f(fmaxf(acc[t][nt][3] + sb[l * F + c + 1], 0.f)));
                        *(float2*)(H + rr * HS + c) = w0;
                        *(float2*)(H + (rr + 8) * HS + c) = w1;
                    }
                }
            }
        } else {
            // ---------- Layer 4, half h of game g ----------
            int u = s - 4 * nG - 4;
            int g = gLo + (u >> 1), h = u & 1;
            const int nT4 = (nw == 0) ? 2 : 1;  // nw0 -> nt{0,1}, nw1 -> nt{2}
            if (h == 0) {
                #pragma unroll
                for (int t = 0; t < 2; ++t)
                    #pragma unroll
                    for (int i = 0; i < 2; ++i)
                        #pragma unroll
                        for (int q2 = 0; q2 < 4; ++q2) acc[t][i][q2] = 0.f;
            }
            #pragma unroll
            for (int kl = 0; kl < 5; ++kl) {
                int kb = h * 40 + kl * 8;
                uint32_t af[2][4];
                af[0][0] = __float_as_uint(H[rA0 * HS + kb + tig]);
                af[0][1] = __float_as_uint(H[(rA0 + 8) * HS + kb + tig]);
                af[0][2] = __float_as_uint(H[rA0 * HS + kb + tig + 4]);
                af[0][3] = __float_as_uint(H[(rA0 + 8) * HS + kb + tig + 4]);
                af[1][0] = __float_as_uint(H[rA1 * HS + kb + tig]);
                af[1][1] = __float_as_uint(H[(rA1 + 8) * HS + kb + tig]);
                af[1][2] = __float_as_uint(H[rA1 * HS + kb + tig + 4]);
                af[1][3] = __float_as_uint(H[(rA1 + 8) * HS + kb + tig + 4]);
                #pragma unroll
                for (int i = 0; i < 2; ++i) {
                    if (i < nT4) {
                        int ntG = nw * 2 + i;
                        // rows >= 18 read stale finite slot data; outputs masked below
                        float2 bp = *(const float2*)(SWp + (ntG * 8 + gid) * WP + kl * 8 + 2 * tig);
                        uint32_t b0 = __float_as_uint(bp.x);
                        uint32_t bv = __float_as_uint(bp.y);
                        mma8(acc[0][i], af[0][0], af[0][1], af[0][2], af[0][3], b0, bv);
                        mma8(acc[1][i], af[1][0], af[1][1], af[1][2], af[1][3], b0, bv);
                    }
                }
            }
            if (h == 1) {
                #pragma unroll
                for (int i = 0; i < 2; ++i) {
                    if (i < nT4) {
                        int ntG = nw * 2 + i;
                        int c = ntG * 8 + 2 * tig;
                        if (c < A) {
                            float bb0 = __ldg(&b4[g * A + c]);
                            float bb1 = __ldg(&b4[g * A + c + 1]);
                            #pragma unroll
                            for (int t = 0; t < 2; ++t) {
                                int rr = (t == 0) ? rA0 : rA1;
                                if (mg[t][0] == g) {
                                    float2 v = make_float2(acc[t][i][0] + bb0, acc[t][i][1] + bb1);
                                    *(float2*)(out + (size_t)(mBase + rr) * A + c) = v;
                                }
                                if (mg[t][1] == g) {
                                    float2 v = make_float2(acc[t][i][2] + bb0, acc[t][i][3] + bb1);
                                    *(float2*)(out + (size_t)(mBase + rr + 8) * A + c) = v;
                                }
                            }
                        }
                    }
                }
            }
        }

        __syncthreads();  // all consumers of slot s done before it is refilled (s+2)
    }
}

extern "C" void kernel_launch(void* const* d_in, const int* in_sizes, int n_in,
                              void* d_out, int out_size) {
    const float* state = (const float*)d_in[0];
    const int*   idx   = (const int*)d_in[1];
    const float* W1    = (const float*)d_in[2];
    const float* b1    = (const float*)d_in[3];
    const float* W2    = (const float*)d_in[4];
    const float* b2    = (const float*)d_in[5];
    const float* W3    = (const float*)d_in[6];
    const float* b3    = (const float*)d_in[7];
    const float* W4    = (const float*)d_in[8];
    const float* b4    = (const float*)d_in[9];
    float* out = (float*)d_out;

    const int B = in_sizes[1];

    prep_kernel<<<(G * 4 * F * 32 + 255) / 256, 256>>>(W1, W2, W3, W4);

    cudaFuncSetAttribute(fused_kernel, cudaFuncAttributeMaxDynamicSharedMemorySize, SMEM_BYTES);
    int grid = (B + BM - 1) / BM;
    fused_kernel<<<grid, THREADS, SMEM_BYTES>>>(state, idx, b1, b2, b3, b4, out, B);
}

// round 12
// speedup vs baseline: 1.0933x; 1.0933x over previous
#include <cuda_runtime.h>
#include <cstdint>

#define DI __device__ __forceinline__

constexpr int D = 128, G = 8, F = 80, A = 18;
constexpr int BM = 128, THREADS = 256;

constexpr int HS = 104;  // H stride (pair-permuted cols): 104 % 32 == 8 -> conflict-free LDS.64
constexpr int WP = 40;   // weight stride (pair-permuted): 40 % 32 == 8 -> conflict-free LDS.64

constexpr int SLOT   = F * WP;               // 3200 floats per weight slot
constexpr int OFF_H  = 0;                    // 128*104 = 13312 floats
constexpr int OFF_SL = BM * HS;              // 3 rotating weight slots
constexpr int OFF_SB = OFF_SL + 3 * SLOT;    // b2(80)+b3(80)
constexpr int SMEM_FLOATS = OFF_SB + 2 * F;  // 23072
constexpr int SMEM_BYTES  = SMEM_FLOATS * 4; // 92288 B -> 2 CTAs/SM

// pair-permuted, tf32-rounded weight images (layout == staged layout)
__device__ __align__(16) float g_W1p[G * 4 * F * WP];   // [g][q][n][40]
__device__ __align__(16) float g_W23p[2 * 2 * F * WP];  // [l][h][n][40]
__device__ __align__(16) float g_W4p[G * 2 * A * WP];   // [g][h][n][40]

DI uint32_t tf32b(float x) {
    uint32_t r; asm("cvt.rna.tf32.f32 %0, %1;" : "=r"(r) : "f"(x));
    return r;
}
DI float tf32f(float x) { return __uint_as_float(tf32b(x)); }

// column j -> pair-permuted position (pairs (k, k+4) adjacent within 8-blocks)
DI int cpos(int j) { return (j & ~7) + 2 * (j & 3) + ((j >> 2) & 1); }

DI void mma8(float* c, uint32_t a0, uint32_t a1, uint32_t a2, uint32_t a3,
             uint32_t b0, uint32_t b1) {
    asm("mma.sync.aligned.m16n8k8.row.col.f32.tf32.tf32.f32 "
        "{%0,%1,%2,%3}, {%4,%5,%6,%7}, {%8,%9}, {%0,%1,%2,%3};"
        : "+f"(c[0]), "+f"(c[1]), "+f"(c[2]), "+f"(c[3])
        : "r"(a0), "r"(a1), "r"(a2), "r"(a3), "r"(b0), "r"(b1));
}

DI void cpa16(uint32_t dst, const float* src) {
    asm volatile("cp.async.cg.shared.global [%0], [%1], 16;" :: "r"(dst), "l"(src));
}
#define CPA_COMMIT() asm volatile("cp.async.commit_group;" ::: "memory")
#define CPA_WAIT1()  asm volatile("cp.async.wait_group 1;" ::: "memory")

__global__ void prep_kernel(const float* __restrict__ W1, const float* __restrict__ W2,
                            const float* __restrict__ W3, const float* __restrict__ W4) {
    int i = blockIdx.x * blockDim.x + threadIdx.x;
    if (i < G * 4 * F * 32) {  // i = ((g*4+q)*F + n)*32 + j
        int j = i & 31; int q2 = i >> 5;
        int n = q2 % F; q2 /= F;
        int q = q2 & 3; int g = q2 >> 2;
        g_W1p[((g * 4 + q) * F + n) * WP + cpos(j)] =
            tf32f(W1[(size_t)(g * F + n) * D + q * 32 + j]);
    }
    if (i < 2 * 2 * F * 40) {  // i = ((l*2+h)*F + n)*40 + j
        int j = i % 40; int q2 = i / 40;
        int n = q2 % F; q2 /= F;
        int h = q2 & 1; int l = q2 >> 1;
        const float* W = l ? W3 : W2;
        g_W23p[((l * 2 + h) * F + n) * WP + cpos(j)] = tf32f(W[n * F + h * 40 + j]);
    }
    if (i < G * 2 * A * 40) {  // i = ((g*2+h)*A + n)*40 + j
        int j = i % 40; int q2 = i / 40;
        int n = q2 % A; q2 /= A;
        int h = q2 & 1; int g = q2 >> 1;
        g_W4p[((g * 2 + h) * A + n) * WP + cpos(j)] =
            tf32f(W4[(size_t)(g * A + n) * F + h * 40 + j]);
    }
}

// prefetch stage s into slot s%3 (all stages are linear copies of preformatted images)
DI void issue_stage(int s, int gLo, int nG, uint32_t slbase, int tid) {
    uint32_t dst = slbase + (uint32_t)(s % 3) * (SLOT * 4);
    const float* src; int nch;
    if (s < 4 * nG) {
        int g = gLo + (s >> 2), q = s & 3;
        src = g_W1p + (size_t)(g * 4 + q) * F * WP; nch = 800;
    } else {
        int t = s - 4 * nG;
        if (t < 4) { src = g_W23p + (size_t)t * F * WP; nch = 800; }
        else {
            int u = t - 4; int g = gLo + (u >> 1), h = u & 1;
            src = g_W4p + (size_t)(g * 2 + h) * A * WP; nch = 180;
        }
    }
    for (int c = tid; c < nch; c += THREADS)
        cpa16(dst + c * 16, src + c * 4);
}

__global__ __launch_bounds__(THREADS, 2)
void fused_kernel(const float* __restrict__ state, const int* __restrict__ idx,
                  const float* __restrict__ b1, const float* __restrict__ b2,
                  const float* __restrict__ b3, const float* __restrict__ b4,
                  float* __restrict__ out, int nTotal)
{
    extern __shared__ float sm[];
    float* H  = sm + OFF_H;
    float* sb = sm + OFF_SB;  // [0..79]=b2, [80..159]=b3

    uint32_t su;
    asm("{ .reg .u64 t; cvta.to.shared.u64 t, %1; cvt.u32.u64 %0, t; }"
        : "=r"(su) : "l"(sm));
    const uint32_t slbase = su + OFF_SL * 4;

    const int tid  = threadIdx.x;
    const int lane = tid & 31;
    const int wid  = tid >> 5;
    const int gid  = lane >> 2;
    const int tig  = lane & 3;

    // warp owns rows [wid*16, wid*16+16): 1 m16 tile x 10 n-tiles. H rows are warp-private.
    const int r0 = wid * 16 + gid;   // rows r0, r0+8

    const int mBase  = blockIdx.x * BM;
    const int nValid = min(BM, nTotal - mBase);

    const int gLo = __ldg(&idx[mBase]);
    const int gHi = __ldg(&idx[mBase + nValid - 1]);
    const int nG = gHi - gLo + 1;
    const int nStages = 6 * nG + 4;  // 4*nG (W1 quarters) + 4 (W2/W3 halves) + 2*nG (W4 halves)

    const int mgA = (r0     < nValid) ? __ldg(&idx[mBase + r0])     : -1;
    const int mgB = (r0 + 8 < nValid) ? __ldg(&idx[mBase + r0 + 8]) : -1;

    if (tid < 2 * F) sb[tid] = (tid < F) ? b2[tid] : b3[tid - F];

    // clamped state row pointers for layer-1 A fragments
    const float* st0 = state + (size_t)min(mBase + r0,     nTotal - 1) * D;
    const float* st1 = state + (size_t)min(mBase + r0 + 8, nTotal - 1) * D;

    issue_stage(0, gLo, nG, slbase, tid); CPA_COMMIT();
    issue_stage(1, gLo, nG, slbase, tid); CPA_COMMIT();

    float acc[10][4];

    for (int s = 0; s < nStages; ++s) {
        CPA_WAIT1();
        __syncthreads();  // stage s data visible; all consumers of slot (s-1)%3 past barrier
        const float* SWp = sm + OFF_SL + (s % 3) * SLOT;

        if (s < 4 * nG) {
            // ---------- Layer 1, quarter q of game g ----------
            int g = gLo + (s >> 2), q = s & 3;
            if (q == 0) {
                #pragma unroll
                for (int nt = 0; nt < 10; ++nt)
                    #pragma unroll
                    for (int i = 0; i < 4; ++i) acc[nt][i] = 0.f;
            }
            #pragma unroll
            for (int kl = 0; kl < 4; ++kl) {
                int kb = q * 32 + kl * 8;
                uint32_t a0 = tf32b(__ldg(st0 + kb + tig));
                uint32_t a1 = tf32b(__ldg(st1 + kb + tig));
                uint32_t a2 = tf32b(__ldg(st0 + kb + tig + 4));
                uint32_t a3 = tf32b(__ldg(st1 + kb + tig + 4));
                #pragma unroll
                for (int nt = 0; nt < 10; ++nt) {
                    float2 bp = *(const float2*)(SWp + (nt * 8 + gid) * WP + kl * 8 + 2 * tig);
                    mma8(acc[nt], a0, a1, a2, a3,
                         __float_as_uint(bp.x), __float_as_uint(bp.y));
                }
            }
            if (q == 3) {  // masked epilogue -> H (tf32-rounded, pair-permuted cols)
                #pragma unroll
                for (int nt = 0; nt < 10; ++nt) {
                    int c = nt * 8 + 2 * tig;
                    if (mgA == g) {
                        H[r0 * HS + cpos(c)]     = tf32f(fmaxf(acc[nt][0] + __ldg(&b1[g * F + c]),     0.f));
                        H[r0 * HS + cpos(c + 1)] = tf32f(fmaxf(acc[nt][1] + __ldg(&b1[g * F + c + 1]), 0.f));
                    }
                    if (mgB == g) {
                        H[(r0 + 8) * HS + cpos(c)]     = tf32f(fmaxf(acc[nt][2] + __ldg(&b1[g * F + c]),     0.f));
                        H[(r0 + 8) * HS + cpos(c + 1)] = tf32f(fmaxf(acc[nt][3] + __ldg(&b1[g * F + c + 1]), 0.f));
                    }
                }
            }
        } else if (s - 4 * nG < 4) {
            // ---------- Layers 2 & 3, half h (H rows warp-private: in-place safe) ----------
            int t4 = s - 4 * nG;
            int l = t4 >> 1, h = t4 & 1;
            if (h == 0) {
                #pragma unroll
                for (int nt = 0; nt < 10; ++nt)
                    #pragma unroll
                    for (int i = 0; i < 4; ++i) acc[nt][i] = 0.f;
            }
            #pragma unroll
            for (int kl = 0; kl < 5; ++kl) {
                int kb = h * 40 + kl * 8;
                float2 av0 = *(const float2*)(H + r0 * HS + kb + 2 * tig);
                float2 av1 = *(const float2*)(H + (r0 + 8) * HS + kb + 2 * tig);
                uint32_t a0 = __float_as_uint(av0.x);
                uint32_t a1 = __float_as_uint(av1.x);
                uint32_t a2 = __float_as_uint(av0.y);
                uint32_t a3 = __float_as_uint(av1.y);
                #pragma unroll
                for (int nt = 0; nt < 10; ++nt) {
                    float2 bp = *(const float2*)(SWp + (nt * 8 + gid) * WP + kl * 8 + 2 * tig);
                    mma8(acc[nt], a0, a1, a2, a3,
                         __float_as_uint(bp.x), __float_as_uint(bp.y));
                }
            }
            if (h == 1) {  // in-place epilogue: only this warp touches these rows
                #pragma unroll
                for (int nt = 0; nt < 10; ++nt) {
                    int c = nt * 8 + 2 * tig;
                    H[r0 * HS + cpos(c)]           = tf32f(fmaxf(acc[nt][0] + sb[l * F + c],     0.f));
                    H[r0 * HS + cpos(c + 1)]       = tf32f(fmaxf(acc[nt][1] + sb[l * F + c + 1], 0.f));
                    H[(r0 + 8) * HS + cpos(c)]     = tf32f(fmaxf(acc[nt][2] + sb[l * F + c],     0.f));
                    H[(r0 + 8) * HS + cpos(c + 1)] = tf32f(fmaxf(acc[nt][3] + sb[l * F + c + 1], 0.f));
                }
            }
        } else {
            // ---------- Layer 4, half h of game g ----------
            int u = s - 4 * nG - 4;
            int g = gLo + (u >> 1), h = u & 1;
            if (h == 0) {
                #pragma unroll
                for (int nt = 0; nt < 3; ++nt)
                    #pragma unroll
                    for (int i = 0; i < 4; ++i) acc[nt][i] = 0.f;
            }
            #pragma unroll
            for (int kl = 0; kl < 5; ++kl) {
                int kb = h * 40 + kl * 8;
                float2 av0 = *(const float2*)(H + r0 * HS + kb + 2 * tig);
                float2 av1 = *(const float2*)(H + (r0 + 8) * HS + kb + 2 * tig);
                uint32_t a0 = __float_as_uint(av0.x);
                uint32_t a1 = __float_as_uint(av1.x);
                uint32_t a2 = __float_as_uint(av0.y);
                uint32_t a3 = __float_as_uint(av1.y);
                #pragma unroll
                for (int nt = 0; nt < 3; ++nt) {
                    // B rows >= 18 read stale-but-finite slot data; outputs masked below
                    float2 bp = *(const float2*)(SWp + (nt * 8 + gid) * WP + kl * 8 + 2 * tig);
                    mma8(acc[nt], a0, a1, a2, a3,
                         __float_as_uint(bp.x), __float_as_uint(bp.y));
                }
            }
            if (h == 1) {
                #pragma unroll
                for (int nt = 0; nt < 3; ++nt) {
                    int c = nt * 8 + 2 * tig;
                    if (c < A) {  // c even, A even -> c+1 < A too
                        float bb0 = __ldg(&b4[g * A + c]);
                        float bb1 = __ldg(&b4[g * A + c + 1]);
                        if (mgA == g) {
                            float2 v = make_float2(acc[nt][0] + bb0, acc[nt][1] + bb1);
                            *(float2*)(out + (size_t)(mBase + r0) * A + c) = v;
                        }
                        if (mgB == g) {
                            float2 v = make_float2(acc[nt][2] + bb0, acc[nt][3] + bb1);
                            *(float2*)(out + (size_t)(mBase + r0 + 8) * A + c) = v;
                        }
                    }
                }
            }
        }

        if (s + 2 < nStages) issue_stage(s + 2, gLo, nG, slbase, tid);
        CPA_COMMIT();  // ALWAYS commit (empty tail groups keep wait_group counts aligned)
    }
}

extern "C" void kernel_launch(void* const* d_in, const int* in_sizes, int n_in,
                              void* d_out, int out_size) {
    const float* state = (const float*)d_in[0];
    const int*   idx   = (const int*)d_in[1];
    const float* W1    = (const float*)d_in[2];
    const float* b1    = (const float*)d_in[3];
    const float* W2    = (const float*)d_in[4];
    const float* b2    = (const float*)d_in[5];
    const float* W3    = (const float*)d_in[6];
    const float* b3    = (const float*)d_in[7];
    const float* W4    = (const float*)d_in[8];
    const float* b4    = (const float*)d_in[9];
    float* out = (float*)d_out;

    const int B = in_sizes[1];

    prep_kernel<<<(G * 4 * F * 32 + 255) / 256, 256>>>(W1, W2, W3, W4);

    cudaFuncSetAttribute(fused_kernel, cudaFuncAttributeMaxDynamicSharedMemorySize, SMEM_BYTES);
    int grid = (B + BM - 1) / BM;
    fused_kernel<<<grid, THREADS, SMEM_BYTES>>>(state, idx, b1, b2, b3, b4, out, B);
}

// round 13
// speedup vs baseline: 1.3666x; 1.2500x over previous
#include <cuda_runtime.h>
#include <cstdint>

#define DI __device__ __forceinline__

constexpr int D = 128, G = 8, F = 80, A = 18;
constexpr int BM = 128, THREADS = 256;

constexpr int XS = 132;  // X stride (state 128 cols / h 80 cols): 132 % 8 == 4 -> conflict-free LDS.32
constexpr int WP = 40;   // weight stride (pair-permuted): 40 % 32 == 8 -> conflict-free LDS.64

constexpr int SLOT   = F * WP;               // 3200 floats per weight slot
constexpr int OFF_X  = 0;                    // 128*132 = 16896 floats (state, then h in-place)
constexpr int OFF_SL = BM * XS;              // 3 rotating weight slots
constexpr int OFF_SB = OFF_SL + 3 * SLOT;    // b2(80)+b3(80)
constexpr int SMEM_FLOATS = OFF_SB + 2 * F;  // 26656
constexpr int SMEM_BYTES  = SMEM_FLOATS * 4; // 106624 B -> 2 CTAs/SM

// pair-permuted, tf32-rounded weight images (layout == staged layout)
__device__ __align__(16) float g_W1p[G * 4 * F * WP];   // [g][q][n][40]
__device__ __align__(16) float g_W23p[2 * 2 * F * WP];  // [l][h][n][40]
__device__ __align__(16) float g_W4p[G * 2 * A * WP];   // [g][h][n][40]

DI uint32_t tf32b(float x) {
    uint32_t r; asm("cvt.rna.tf32.f32 %0, %1;" : "=r"(r) : "f"(x));
    return r;
}
DI float tf32f(float x) { return __uint_as_float(tf32b(x)); }

// column j -> pair-permuted position (pairs (k, k+4) adjacent within 8-blocks)
DI int cpos(int j) { return (j & ~7) + 2 * (j & 3) + ((j >> 2) & 1); }

DI void mma8(float* c, uint32_t a0, uint32_t a1, uint32_t a2, uint32_t a3,
             uint32_t b0, uint32_t b1) {
    asm("mma.sync.aligned.m16n8k8.row.col.f32.tf32.tf32.f32 "
        "{%0,%1,%2,%3}, {%4,%5,%6,%7}, {%8,%9}, {%0,%1,%2,%3};"
        : "+f"(c[0]), "+f"(c[1]), "+f"(c[2]), "+f"(c[3])
        : "r"(a0), "r"(a1), "r"(a2), "r"(a3), "r"(b0), "r"(b1));
}

DI void cpa16(uint32_t dst, const float* src) {
    asm volatile("cp.async.cg.shared.global [%0], [%1], 16;" :: "r"(dst), "l"(src));
}
#define CPA_COMMIT() asm volatile("cp.async.commit_group;" ::: "memory")
#define CPA_WAIT1()  asm volatile("cp.async.wait_group 1;" ::: "memory")

__global__ void prep_kernel(const float* __restrict__ W1, const float* __restrict__ W2,
                            const float* __restrict__ W3, const float* __restrict__ W4) {
    int i = blockIdx.x * blockDim.x + threadIdx.x;
    if (i < G * 4 * F * 32) {  // i = ((g*4+q)*F + n)*32 + j
        int j = i & 31; int q2 = i >> 5;
        int n = q2 % F; q2 /= F;
        int q = q2 & 3; int g = q2 >> 2;
        g_W1p[((g * 4 + q) * F + n) * WP + cpos(j)] =
            tf32f(W1[(size_t)(g * F + n) * D + q * 32 + j]);
    }
    if (i < 2 * 2 * F * 40) {  // i = ((l*2+h)*F + n)*40 + j
        int j = i % 40; int q2 = i / 40;
        int n = q2 % F; q2 /= F;
        int h = q2 & 1; int l = q2 >> 1;
        const float* W = l ? W3 : W2;
        g_W23p[((l * 2 + h) * F + n) * WP + cpos(j)] = tf32f(W[n * F + h * 40 + j]);
    }
    if (i < G * 2 * A * 40) {  // i = ((g*2+h)*A + n)*40 + j
        int j = i % 40; int q2 = i / 40;
        int n = q2 % A; q2 /= A;
        int h = q2 & 1; int g = q2 >> 1;
        g_W4p[((g * 2 + h) * A + n) * WP + cpos(j)] =
            tf32f(W4[(size_t)(g * A + n) * F + h * 40 + j]);
    }
}

// prefetch stage s into slot s%3 (linear copies of preformatted images)
DI void issue_stage(int s, int gLo, int nG, uint32_t slbase, int tid) {
    uint32_t dst = slbase + (uint32_t)(s % 3) * (SLOT * 4);
    const float* src; int nch;
    if (s < 4 * nG) {
        int g = gLo + (s >> 2), q = s & 3;
        src = g_W1p + (size_t)(g * 4 + q) * F * WP; nch = 800;
    } else {
        int t = s - 4 * nG;
        if (t < 4) { src = g_W23p + (size_t)t * F * WP; nch = 800; }
        else {
            int u = t - 4; int g = gLo + (u >> 1), h = u & 1;
            src = g_W4p + (size_t)(g * 2 + h) * A * WP; nch = 180;
        }
    }
    for (int c = tid; c < nch; c += THREADS)
        cpa16(dst + c * 16, src + c * 4);
}

__global__ __launch_bounds__(THREADS, 2)
void fused_kernel(const float* __restrict__ state, const int* __restrict__ idx,
                  const float* __restrict__ b1, const float* __restrict__ b2,
                  const float* __restrict__ b3, const float* __restrict__ b4,
                  float* __restrict__ out, int nTotal)
{
    extern __shared__ float sm[];
    float* X  = sm + OFF_X;   // state (cols 0..127), overwritten per-row by h (cols 0..79)
    float* sb = sm + OFF_SB;  // [0..79]=b2, [80..159]=b3

    uint32_t su;
    asm("{ .reg .u64 t; cvta.to.shared.u64 t, %1; cvt.u32.u64 %0, t; }"
        : "=r"(su) : "l"(sm));
    const uint32_t slbase = su + OFF_SL * 4;

    const int tid  = threadIdx.x;
    const int lane = tid & 31;
    const int wid  = tid >> 5;
    const int gid  = lane >> 2;
    const int tig  = lane & 3;

    // warp owns rows [wid*16, wid*16+16): X rows are warp-private in every layer
    const int r0 = wid * 16 + gid;   // rows r0, r0+8

    const int mBase  = blockIdx.x * BM;
    const int nValid = min(BM, nTotal - mBase);

    const int gLo = __ldg(&idx[mBase]);
    const int gHi = __ldg(&idx[mBase + nValid - 1]);
    const int nG = gHi - gLo + 1;
    const int nStages = 6 * nG + 4;  // 4*nG (W1 quarters) + 4 (W2/W3 halves) + 2*nG (W4 halves)

    const int mgA = (r0     < nValid) ? __ldg(&idx[mBase + r0])     : -1;
    const int mgB = (r0 + 8 < nValid) ? __ldg(&idx[mBase + r0 + 8]) : -1;

    if (tid < 2 * F) sb[tid] = (tid < F) ? b2[tid] : b3[tid - F];

    // ---- prologue: stage full state tile (coalesced) + weight stage 0 -> group 0 ----
    for (int c = tid; c < BM * 32; c += THREADS) {
        int m = c >> 5, cc = c & 31;
        int row = min(mBase + m, nTotal - 1);
        cpa16(su + (uint32_t)(m * XS + cc * 4) * 4, state + (size_t)row * D + cc * 4);
    }
    issue_stage(0, gLo, nG, slbase, tid); CPA_COMMIT();
    issue_stage(1, gLo, nG, slbase, tid); CPA_COMMIT();

    float acc[10][4];

    for (int s = 0; s < nStages; ++s) {
        CPA_WAIT1();
        __syncthreads();  // stage s data (and, at s=0, the state tile) visible to all
        const float* SWp = sm + OFF_SL + (s % 3) * SLOT;

        if (s < 4 * nG) {
            // ---------- Layer 1, quarter q of game g (A from X state cols) ----------
            int g = gLo + (s >> 2), q = s & 3;
            if (q == 0) {
                #pragma unroll
                for (int nt = 0; nt < 10; ++nt)
                    #pragma unroll
                    for (int i = 0; i < 4; ++i) acc[nt][i] = 0.f;
            }
            #pragma unroll
            for (int kl = 0; kl < 4; ++kl) {
                int kb = q * 32 + kl * 8;
                uint32_t a0 = tf32b(X[r0 * XS + kb + tig]);
                uint32_t a1 = tf32b(X[(r0 + 8) * XS + kb + tig]);
                uint32_t a2 = tf32b(X[r0 * XS + kb + tig + 4]);
                uint32_t a3 = tf32b(X[(r0 + 8) * XS + kb + tig + 4]);
                #pragma unroll
                for (int nt = 0; nt < 10; ++nt) {
                    float2 bp = *(const float2*)(SWp + (nt * 8 + gid) * WP + kl * 8 + 2 * tig);
                    mma8(acc[nt], a0, a1, a2, a3,
                         __float_as_uint(bp.x), __float_as_uint(bp.y));
                }
            }
            if (q == 3) {
                // masked epilogue: overwrite this row's state cols 0..79 with h1.
                // Row's state is dead once its game's layer-1 output is complete;
                // other games' reads of these rows are masked garbage (finite).
                #pragma unroll
                for (int nt = 0; nt < 10; ++nt) {
                    int c = nt * 8 + 2 * tig;
                    if (mgA == g) {
                        float2 w = make_float2(
                            tf32f(fmaxf(acc[nt][0] + __ldg(&b1[g * F + c]),     0.f)),
                            tf32f(fmaxf(acc[nt][1] + __ldg(&b1[g * F + c + 1]), 0.f)));
                        *(float2*)(X + r0 * XS + c) = w;
                    }
                    if (mgB == g) {
                        float2 w = make_float2(
                            tf32f(fmaxf(acc[nt][2] + __ldg(&b1[g * F + c]),     0.f)),
                            tf32f(fmaxf(acc[nt][3] + __ldg(&b1[g * F + c + 1]), 0.f)));
                        *(float2*)(X + (r0 + 8) * XS + c) = w;
                    }
                }
            }
        } else if (s - 4 * nG < 4) {
            // ---------- Layers 2 & 3, half h (X rows warp-private: in-place safe) ----------
            int t4 = s - 4 * nG;
            int l = t4 >> 1, h = t4 & 1;
            if (h == 0) {
                #pragma unroll
                for (int nt = 0; nt < 10; ++nt)
                    #pragma unroll
                    for (int i = 0; i < 4; ++i) acc[nt][i] = 0.f;
            }
            #pragma unroll
            for (int kl = 0; kl < 5; ++kl) {
                int kb = h * 40 + kl * 8;
                uint32_t a0 = __float_as_uint(X[r0 * XS + kb + tig]);
                uint32_t a1 = __float_as_uint(X[(r0 + 8) * XS + kb + tig]);
                uint32_t a2 = __float_as_uint(X[r0 * XS + kb + tig + 4]);
                uint32_t a3 = __float_as_uint(X[(r0 + 8) * XS + kb + tig + 4]);
                #pragma unroll
                for (int nt = 0; nt < 10; ++nt) {
                    float2 bp = *(const float2*)(SWp + (nt * 8 + gid) * WP + kl * 8 + 2 * tig);
                    mma8(acc[nt], a0, a1, a2, a3,
                         __float_as_uint(bp.x), __float_as_uint(bp.y));
                }
            }
            if (h == 1) {  // in-place epilogue: only this warp touches these rows
                #pragma unroll
                for (int nt = 0; nt < 10; ++nt) {
                    int c = nt * 8 + 2 * tig;
                    float2 w0 = make_float2(
                        tf32f(fmaxf(acc[nt][0] + sb[l * F + c],     0.f)),
                        tf32f(fmaxf(acc[nt][1] + sb[l * F + c + 1], 0.f)));
                    float2 w1 = make_float2(
                        tf32f(fmaxf(acc[nt][2] + sb[l * F + c],     0.f)),
                        tf32f(fmaxf(acc[nt][3] + sb[l * F + c + 1], 0.f)));
                    *(float2*)(X + r0 * XS + c) = w0;
                    *(float2*)(X + (r0 + 8) * XS + c) = w1;
                }
            }
        } else {
            // ---------- Layer 4, half h of game g ----------
            int u = s - 4 * nG - 4;
            int g = gLo + (u >> 1), h = u & 1;
            if (h == 0) {
                #pragma unroll
                for (int nt = 0; nt < 3; ++nt)
                    #pragma unroll
                    for (int i = 0; i < 4; ++i) acc[nt][i] = 0.f;
            }
            #pragma unroll
            for (int kl = 0; kl < 5; ++kl) {
                int kb = h * 40 + kl * 8;
                uint32_t a0 = __float_as_uint(X[r0 * XS + kb + tig]);
                uint32_t a1 = __float_as_uint(X[(r0 + 8) * XS + kb + tig]);
                uint32_t a2 = __float_as_uint(X[r0 * XS + kb + tig + 4]);
                uint32_t a3 = __float_as_uint(X[(r0 + 8) * XS + kb + tig + 4]);
                #pragma unroll
                for (int nt = 0; nt < 3; ++nt) {
                    // B rows >= 18 read stale-but-finite slot data; outputs masked below
                    float2 bp = *(const float2*)(SWp + (nt * 8 + gid) * WP + kl * 8 + 2 * tig);
                    mma8(acc[nt], a0, a1, a2, a3,
                         __float_as_uint(bp.x), __float_as_uint(bp.y));
                }
            }
            if (h == 1) {
                #pragma unroll
                for (int nt = 0; nt < 3; ++nt) {
                    int c = nt * 8 + 2 * tig;
                    if (c < A) {  // c even, A even -> c+1 < A too
                        float bb0 = __ldg(&b4[g * A + c]);
                        float bb1 = __ldg(&b4[g * A + c + 1]);
                        if (mgA == g) {
                            float2 v = make_float2(acc[nt][0] + bb0, acc[nt][1] + bb1);
                            *(float2*)(out + (size_t)(mBase + r0) * A + c) = v;
                        }
                        if (mgB == g) {
                            float2 v = make_float2(acc[nt][2] + bb0, acc[nt][3] + bb1);
                            *(float2*)(out + (size_t)(mBase + r0 + 8) * A + c) = v;
                        }
                    }
                }
            }
        }

        if (s + 2 < nStages) issue_stage(s + 2, gLo, nG, slbase, tid);
        CPA_COMMIT();  // ALWAYS commit (empty tail groups keep wait_group counts aligned)
    }
}

extern "C" void kernel_launch(void* const* d_in, const int* in_sizes, int n_in,
                              void* d_out, int out_size) {
    const float* state = (const float*)d_in[0];
    const int*   idx   = (const int*)d_in[1];
    const float* W1    = (const float*)d_in[2];
    const float* b1    = (const float*)d_in[3];
    const float* W2    = (const float*)d_in[4];
    const float* b2    = (const float*)d_in[5];
    const float* W3    = (const float*)d_in[6];
    const float* b3    = (const float*)d_in[7];
    const float* W4    = (const float*)d_in[8];
    const float* b4    = (const float*)d_in[9];
    float* out = (float*)d_out;

    const int B = in_sizes[1];

    prep_kernel<<<(G * 4 * F * 32 + 255) / 256, 256>>>(W1, W2, W3, W4);

    cudaFuncSetAttribute(fused_kernel, cudaFuncAttributeMaxDynamicSharedMemorySize, SMEM_BYTES);
    int grid = (B + BM - 1) / BM;
    fused_kernel<<<grid, THREADS, SMEM_BYTES>>>(state, idx, b1, b2, b3, b4, out, B);
}

// round 14
// speedup vs baseline: 1.4371x; 1.0516x over previous
#include <cuda_runtime.h>
#include <cstdint>

#define DI __device__ __forceinline__

constexpr int D = 128, G = 8, F = 80, A = 18;
constexpr int BM = 128, THREADS = 256;

constexpr int XS = 132;  // X stride (state/h): 132 % 8 == 4 -> conflict-free LDS.32 frags
constexpr int WP = 40;   // weight stride (pair-permuted): 40 % 32 == 8 -> conflict-free LDS.64

constexpr int SLOT   = F * WP;               // 3200 floats per weight slot
constexpr int OFF_X  = 0;                    // 128*132 floats (state, then h in-place)
constexpr int OFF_SL = BM * XS;              // 3 rotating weight slots
constexpr int OFF_SB = OFF_SL + 3 * SLOT;    // b2(80)+b3(80)
constexpr int SMEM_FLOATS = OFF_SB + 2 * F;
constexpr int SMEM_BYTES  = SMEM_FLOATS * 4; // 106624 B -> 2 CTAs/SM

// pair-permuted, tf32-rounded weight images (layout == staged layout)
__device__ __align__(16) float g_W1p[G * 4 * F * WP];   // [g][q][n][40]
__device__ __align__(16) float g_W23p[2 * 2 * F * WP];  // [l][h][n][40]
__device__ __align__(16) float g_W4p[G * 2 * A * WP];   // [g][h][n][40]

DI uint32_t tf32b(float x) {
    uint32_t r; asm("cvt.rna.tf32.f32 %0, %1;" : "=r"(r) : "f"(x));
    return r;
}
DI float tf32f(float x) { return __uint_as_float(tf32b(x)); }

// column j -> pair-permuted position (pairs (k, k+4) adjacent within 8-blocks)
DI int cpos(int j) { return (j & ~7) + 2 * (j & 3) + ((j >> 2) & 1); }

DI void mma8(float* c, uint32_t a0, uint32_t a1, uint32_t a2, uint32_t a3,
             uint32_t b0, uint32_t b1) {
    asm("mma.sync.aligned.m16n8k8.row.col.f32.tf32.tf32.f32 "
        "{%0,%1,%2,%3}, {%4,%5,%6,%7}, {%8,%9}, {%0,%1,%2,%3};"
        : "+f"(c[0]), "+f"(c[1]), "+f"(c[2]), "+f"(c[3])
        : "r"(a0), "r"(a1), "r"(a2), "r"(a3), "r"(b0), "r"(b1));
}

DI void cpa16(uint32_t dst, const float* src) {
    asm volatile("cp.async.cg.shared.global [%0], [%1], 16;" :: "r"(dst), "l"(src));
}
#define CPA_COMMIT() asm volatile("cp.async.commit_group;" ::: "memory")
#define CPA_WAIT1()  asm volatile("cp.async.wait_group 1;" ::: "memory")

__global__ void prep_kernel(const float* __restrict__ W1, const float* __restrict__ W2,
                            const float* __restrict__ W3, const float* __restrict__ W4) {
    int i = blockIdx.x * blockDim.x + threadIdx.x;
    if (i < G * 4 * F * 32) {  // i = ((g*4+q)*F + n)*32 + j
        int j = i & 31; int q2 = i >> 5;
        int n = q2 % F; q2 /= F;
        int q = q2 & 3; int g = q2 >> 2;
        g_W1p[((g * 4 + q) * F + n) * WP + cpos(j)] =
            tf32f(W1[(size_t)(g * F + n) * D + q * 32 + j]);
    }
    if (i < 2 * 2 * F * 40) {  // i = ((l*2+h)*F + n)*40 + j
        int j = i % 40; int q2 = i / 40;
        int n = q2 % F; q2 /= F;
        int h = q2 & 1; int l = q2 >> 1;
        const float* W = l ? W3 : W2;
        g_W23p[((l * 2 + h) * F + n) * WP + cpos(j)] = tf32f(W[n * F + h * 40 + j]);
    }
    if (i < G * 2 * A * 40) {  // i = ((g*2+h)*A + n)*40 + j
        int j = i % 40; int q2 = i / 40;
        int n = q2 % A; q2 /= A;
        int h = q2 & 1; int g = q2 >> 1;
        g_W4p[((g * 2 + h) * A + n) * WP + cpos(j)] =
            tf32f(W4[(size_t)(g * A + n) * F + h * 40 + j]);
    }
}

// prefetch stage s into slot s%3 (linear copies of preformatted images)
DI void issue_stage(int s, int gLo, int nG, uint32_t slbase, int tid) {
    uint32_t dst = slbase + (uint32_t)(s % 3) * (SLOT * 4);
    const float* src; int nch;
    if (s < 4 * nG) {
        int g = gLo + (s >> 2), q = s & 3;
        src = g_W1p + (size_t)(g * 4 + q) * F * WP; nch = 800;
    } else {
        int t = s - 4 * nG;
        if (t < 4) { src = g_W23p + (size_t)t * F * WP; nch = 800; }
        else {
            int u = t - 4; int g = gLo + (u >> 1), h = u & 1;
            src = g_W4p + (size_t)(g * 2 + h) * A * WP; nch = 180;
        }
    }
    for (int c = tid; c < nch; c += THREADS)
        cpa16(dst + c * 16, src + c * 4);
}

__global__ __launch_bounds__(THREADS, 2)
void fused_kernel(const float* __restrict__ state, const int* __restrict__ idx,
                  const float* __restrict__ b1, const float* __restrict__ b2,
                  const float* __restrict__ b3, const float* __restrict__ b4,
                  float* __restrict__ out, int nTotal)
{
    extern __shared__ float sm[];
    float* X  = sm + OFF_X;   // state (cols 0..127), overwritten per-row by h (cols 0..79)
    float* sb = sm + OFF_SB;  // [0..79]=b2, [80..159]=b3

    uint32_t su;
    asm("{ .reg .u64 t; cvta.to.shared.u64 t, %1; cvt.u32.u64 %0, t; }"
        : "=r"(su) : "l"(sm));
    const uint32_t slbase = su + OFF_SL * 4;

    const int tid  = threadIdx.x;
    const int lane = tid & 31;
    const int wid  = tid >> 5;
    const int gid  = lane >> 2;
    const int tig  = lane & 3;

    // 4 m-warps x 2 n-warps; each warp: 2 m16 tiles x 5 n-tiles (its 40 cols)
    const int mw = wid & 3;
    const int nw = wid >> 2;
    const int nbase = nw * 40;
    const int rA0 = mw * 32 + gid;        // m-tile 0: rows rA0, rA0+8
    const int rA1 = mw * 32 + 16 + gid;   // m-tile 1: rows rA1, rA1+8

    const int mBase  = blockIdx.x * BM;
    const int nValid = min(BM, nTotal - mBase);

    const int gLo = __ldg(&idx[mBase]);
    const int gHi = __ldg(&idx[mBase + nValid - 1]);
    const int nG = gHi - gLo + 1;
    const int nStages = 6 * nG + 4;  // 4*nG (W1 quarters) + 4 (W2/W3 halves) + 2*nG (W4 halves)

    int mg[2][2];
    mg[0][0] = (rA0     < nValid) ? __ldg(&idx[mBase + rA0])     : -1;
    mg[0][1] = (rA0 + 8 < nValid) ? __ldg(&idx[mBase + rA0 + 8]) : -1;
    mg[1][0] = (rA1     < nValid) ? __ldg(&idx[mBase + rA1])     : -1;
    mg[1][1] = (rA1 + 8 < nValid) ? __ldg(&idx[mBase + rA1 + 8]) : -1;

    if (tid < 2 * F) sb[tid] = (tid < F) ? b2[tid] : b3[tid - F];

    // ---- prologue: stage full state tile (coalesced) + weight stages 0,1 ----
    for (int c = tid; c < BM * 32; c += THREADS) {
        int m = c >> 5, cc = c & 31;
        int row = min(mBase + m, nTotal - 1);
        cpa16(su + (uint32_t)(m * XS + cc * 4) * 4, state + (size_t)row * D + cc * 4);
    }
    issue_stage(0, gLo, nG, slbase, tid); CPA_COMMIT();
    issue_stage(1, gLo, nG, slbase, tid); CPA_COMMIT();

    float acc[2][5][4];

    for (int s = 0; s < nStages; ++s) {
        CPA_WAIT1();
        __syncthreads();  // stage s data (and, at s=0, the state tile) visible to all
        const float* SWp = sm + OFF_SL + (s % 3) * SLOT;

        if (s < 4 * nG) {
            // ---------- Layer 1, quarter q of game g (A from X state cols) ----------
            int g = gLo + (s >> 2), q = s & 3;
            if (q == 0) {
                #pragma unroll
                for (int t = 0; t < 2; ++t)
                    #pragma unroll
                    for (int nt = 0; nt < 5; ++nt)
                        #pragma unroll
                        for (int i = 0; i < 4; ++i) acc[t][nt][i] = 0.f;
            }
            #pragma unroll
            for (int kl = 0; kl < 4; ++kl) {
                int kb = q * 32 + kl * 8;
                uint32_t af[2][4];
                af[0][0] = tf32b(X[rA0 * XS + kb + tig]);
                af[0][1] = tf32b(X[(rA0 + 8) * XS + kb + tig]);
                af[0][2] = tf32b(X[rA0 * XS + kb + tig + 4]);
                af[0][3] = tf32b(X[(rA0 + 8) * XS + kb + tig + 4]);
                af[1][0] = tf32b(X[rA1 * XS + kb + tig]);
                af[1][1] = tf32b(X[(rA1 + 8) * XS + kb + tig]);
                af[1][2] = tf32b(X[rA1 * XS + kb + tig + 4]);
                af[1][3] = tf32b(X[(rA1 + 8) * XS + kb + tig + 4]);
                #pragma unroll
                for (int nt = 0; nt < 5; ++nt) {
                    float2 bp = *(const float2*)(SWp + (nbase + nt * 8 + gid) * WP + kl * 8 + 2 * tig);
                    uint32_t b0 = __float_as_uint(bp.x);
                    uint32_t bv = __float_as_uint(bp.y);
                    mma8(acc[0][nt], af[0][0], af[0][1], af[0][2], af[0][3], b0, bv);
                    mma8(acc[1][nt], af[1][0], af[1][1], af[1][2], af[1][3], b0, bv);
                }
            }
            if (q == 3) {
                // masked epilogue: overwrite this row's state cols (own 40) with h1.
                // Writes cols 0..79 are disjoint from q=3 MMA reads (cols 96..127): no barrier.
                #pragma unroll
                for (int t = 0; t < 2; ++t) {
                    int rr = (t == 0) ? rA0 : rA1;
                    #pragma unroll
                    for (int hf = 0; hf < 2; ++hf) {
                        if (mg[t][hf] == g) {
                            int row = rr + hf * 8;
                            #pragma unroll
                            for (int nt = 0; nt < 5; ++nt) {
                                int c = nbase + nt * 8 + 2 * tig;
                                float2 w = make_float2(
                                    tf32f(fmaxf(acc[t][nt][2 * hf]     + __ldg(&b1[g * F + c]),     0.f)),
                                    tf32f(fmaxf(acc[t][nt][2 * hf + 1] + __ldg(&b1[g * F + c + 1]), 0.f)));
                                *(float2*)(X + row * XS + c) = w;
                            }
                        }
                    }
                }
            }
        } else if (s - 4 * nG < 4) {
            // ---------- Layers 2 & 3, half h ----------
            int t4 = s - 4 * nG;
            int l = t4 >> 1, h = t4 & 1;
            if (h == 0) {
                #pragma unroll
                for (int t = 0; t < 2; ++t)
                    #pragma unroll
                    for (int nt = 0; nt < 5; ++nt)
                        #pragma unroll
                        for (int i = 0; i < 4; ++i) acc[t][nt][i] = 0.f;
            }
            #pragma unroll
            for (int kl = 0; kl < 5; ++kl) {
                int kb = h * 40 + kl * 8;
                uint32_t af[2][4];
                af[0][0] = __float_as_uint(X[rA0 * XS + kb + tig]);
                af[0][1] = __float_as_uint(X[(rA0 + 8) * XS + kb + tig]);
                af[0][2] = __float_as_uint(X[rA0 * XS + kb + tig + 4]);
                af[0][3] = __float_as_uint(X[(rA0 + 8) * XS + kb + tig + 4]);
                af[1][0] = __float_as_uint(X[rA1 * XS + kb + tig]);
                af[1][1] = __float_as_uint(X[(rA1 + 8) * XS + kb + tig]);
                af[1][2] = __float_as_uint(X[rA1 * XS + kb + tig + 4]);
                af[1][3] = __float_as_uint(X[(rA1 + 8) * XS + kb + tig + 4]);
                #pragma unroll
                for (int nt = 0; nt < 5; ++nt) {
                    float2 bp = *(const float2*)(SWp + (nbase + nt * 8 + gid) * WP + kl * 8 + 2 * tig);
                    uint32_t b0 = __float_as_uint(bp.x);
                    uint32_t bv = __float_as_uint(bp.y);
                    mma8(acc[0][nt], af[0][0], af[0][1], af[0][2], af[0][3], b0, bv);
                    mma8(acc[1][nt], af[1][0], af[1][1], af[1][2], af[1][3], b0, bv);
                }
            }
            if (h == 1) {
                // In-place update of X rows shared between the two n-warps:
                // all warps must finish reading old h before anyone overwrites.
                __syncthreads();
                #pragma unroll
                for (int t = 0; t < 2; ++t) {
                    int rr = (t == 0) ? rA0 : rA1;
                    #pragma unroll
                    for (int nt = 0; nt < 5; ++nt) {
                        int c = nbase + nt * 8 + 2 * tig;
                        float2 w0 = make_float2(
                            tf32f(fmaxf(acc[t][nt][0] + sb[l * F + c],     0.f)),
                            tf32f(fmaxf(acc[t][nt][1] + sb[l * F + c + 1], 0.f)));
                        float2 w1 = make_float2(
                            tf32f(fmaxf(acc[t][nt][2] + sb[l * F + c],     0.f)),
                            tf32f(fmaxf(acc[t][nt][3] + sb[l * F + c + 1], 0.f)));
                        *(float2*)(X + rr * XS + c) = w0;
                        *(float2*)(X + (rr + 8) * XS + c) = w1;
                    }
                }
            }
        } else {
            // ---------- Layer 4, half h of game g (writes only to global) ----------
            int u = s - 4 * nG - 4;
            int g = gLo + (u >> 1), h = u & 1;
            const int nT4 = (nw == 0) ? 2 : 1;  // nw0 -> nt{0,1}, nw1 -> nt{2}
            if (h == 0) {
                #pragma unroll
                for (int t = 0; t < 2; ++t)
                    #pragma unroll
                    for (int i = 0; i < 2; ++i)
                        #pragma unroll
                        for (int q2 = 0; q2 < 4; ++q2) acc[t][i][q2] = 0.f;
            }
            #pragma unroll
            for (int kl = 0; kl < 5; ++kl) {
                int kb = h * 40 + kl * 8;
                uint32_t af[2][4];
                af[0][0] = __float_as_uint(X[rA0 * XS + kb + tig]);
                af[0][1] = __float_as_uint(X[(rA0 + 8) * XS + kb + tig]);
                af[0][2] = __float_as_uint(X[rA0 * XS + kb + tig + 4]);
                af[0][3] = __float_as_uint(X[(rA0 + 8) * XS + kb + tig + 4]);
                af[1][0] = __float_as_uint(X[rA1 * XS + kb + tig]);
                af[1][1] = __float_as_uint(X[(rA1 + 8) * XS + kb + tig]);
                af[1][2] = __float_as_uint(X[rA1 * XS + kb + tig + 4]);
                af[1][3] = __float_as_uint(X[(rA1 + 8) * XS + kb + tig + 4]);
                #pragma unroll
                for (int i = 0; i < 2; ++i) {
                    if (i < nT4) {
                        int ntG = nw * 2 + i;
                        // B rows >= 18 read stale-but-finite slot data; outputs masked below
                        float2 bp = *(const float2*)(SWp + (ntG * 8 + gid) * WP + kl * 8 + 2 * tig);
                        uint32_t b0 = __float_as_uint(bp.x);
                        uint32_t bv = __float_as_uint(bp.y);
                        mma8(acc[0][i], af[0][0], af[0][1], af[0][2], af[0][3], b0, bv);
                        mma8(acc[1][i], af[1][0], af[1][1], af[1][2], af[1][3], b0, bv);
                    }
                }
            }
            if (h == 1) {
                #pragma unroll
                for (int i = 0; i < 2; ++i) {
                    if (i < nT4) {
                        int ntG = nw * 2 + i;
                        int c = ntG * 8 + 2 * tig;
                        if (c < A) {  // c even, A even -> c+1 < A too
                            float bb0 = __ldg(&b4[g * A + c]);
                            float bb1 = __ldg(&b4[g * A + c + 1]);
                            #pragma unroll
                            for (int t = 0; t < 2; ++t) {
                                int rr = (t == 0) ? rA0 : rA1;
                                if (mg[t][0] == g) {
                                    float2 v = make_float2(acc[t][i][0] + bb0, acc[t][i][1] + bb1);
                                    *(float2*)(out + (size_t)(mBase + rr) * A + c) = v;
                                }
                                if (mg[t][1] == g) {
                                    float2 v = make_float2(acc[t][i][2] + bb0, acc[t][i][3] + bb1);
                                    *(float2*)(out + (size_t)(mBase + rr + 8) * A + c) = v;
                                }
                            }
                        }
                    }
                }
            }
        }

        if (s + 2 < nStages) issue_stage(s + 2, gLo, nG, slbase, tid);
        CPA_COMMIT();  // ALWAYS commit (empty tail groups keep wait_group counts aligned)
    }
}

extern "C" void kernel_launch(void* const* d_in, const int* in_sizes, int n_in,
                              void* d_out, int out_size) {
    const float* state = (const float*)d_in[0];
    const int*   idx   = (const int*)d_in[1];
    const float* W1    = (const float*)d_in[2];
    const float* b1    = (const float*)d_in[3];
    const float* W2    = (const float*)d_in[4];
    const float* b2    = (const float*)d_in[5];
    const float* W3    = (const float*)d_in[6];
    const float* b3    = (const float*)d_in[7];
    const float* W4    = (const float*)d_in[8];
    const float* b4    = (const float*)d_in[9];
    float* out = (float*)d_out;

    const int B = in_sizes[1];

    prep_kernel<<<(G * 4 * F * 32 + 255) / 256, 256>>>(W1, W2, W3, W4);

    cudaFuncSetAttribute(fused_kernel, cudaFuncAttributeMaxDynamicSharedMemorySize, SMEM_BYTES);
    int grid = (B + BM - 1) / BM;
    fused_kernel<<<grid, THREADS, SMEM_BYTES>>>(state, idx, b1, b2, b3, b4, out, B);
}